// round 9
// baseline (speedup 1.0000x reference)
#include <cuda_runtime.h>
#include <cuda_bf16.h>
#include <cstdint>

#define CH    512
#define FH    64
#define FW    96
#define HW    6144          // 64*96
#define KDIM  4608          // 512*9
#define NANCH 55296         // HW*9
#define NSORT 65536
#define PRE_NMS  6000
#define POST_NMS 300

typedef unsigned long long u64;
typedef unsigned int u32;

// ------------- device scratch (no allocation allowed) -------------
__device__ float g_x[CH * HW];        // conv1 output (relu), [c][n]
__device__ float4 g_boxes[NANCH];
__device__ u64   g_keys[NSORT];

// base anchors, exact per reference _base_anchors():
// ratio 0.5: (w,h)=(23,12); ratio 1.0: (16,16); ratio 2.0: (11,22)
// scaled by 8/16/32 about center (7.5,7.5).
// Row 8 y2 corrected this round: 7.5 + 0.5*(704-1) = 359 (was 375).
__constant__ float c_anch[36] = {
    -84.f,  -40.f,  99.f,  55.f,
   -176.f,  -88.f, 191.f, 103.f,
   -360.f, -184.f, 375.f, 199.f,
    -56.f,  -56.f,  71.f,  71.f,
   -120.f, -120.f, 135.f, 135.f,
   -248.f, -248.f, 263.f, 263.f,
    -36.f,  -80.f,  51.f,  95.f,
    -80.f, -168.f,  95.f, 183.f,
   -168.f, -344.f, 183.f, 359.f
};

// ------------- packed fp32x2 helpers -------------
__device__ __forceinline__ u64 ffma2(u64 a, u64 b, u64 c) {
    u64 d;
    asm("fma.rn.f32x2 %0, %1, %2, %3;" : "=l"(d) : "l"(a), "l"(b), "l"(c));
    return d;
}
__device__ __forceinline__ u64 dup2(float v) {
    u32 u = __float_as_uint(v);
    return ((u64)u << 32) | (u64)u;
}

// =====================================================================
// Kernel 1: 3x3 conv 512->512 + bias + relu, implicit GEMM.
// M=512(co) x N=6144(pixel) x K=4608(ci*9+kh*3+kw)
// tile 64M x 128N, BK=16, 128 threads, micro 8M x 8N via FFMA2.
// A (weights) stored DUPLICATED in smem; B pairs come naturally.
// =====================================================================
__global__ void __launch_bounds__(128) conv3_kernel(
        const float* __restrict__ feat,   // [512][64][96]
        const float* __restrict__ w,      // [512][4608]
        const float* __restrict__ bias) {
    __shared__ __align__(16) float As2[16][128];  // [k][2*m] duplicated pairs
    __shared__ __align__(16) float Bs [16][128];  // [k][n]

    const int tid = threadIdx.x;
    const int n0  = blockIdx.x * 128;
    const int co0 = blockIdx.y * 64;
    const int tng = tid & 15;     // 16 N-groups of 8
    const int tmg = tid >> 4;     // 8  M-groups of 8

    // A loader mapping: m = tid>>1 (0..63), kq = (tid&1)*8
    const int a_m  = tid >> 1;
    const int a_kq = (tid & 1) * 8;
    const float* a_src = w + (size_t)(co0 + a_m) * KDIM;

    // B loader mapping: fixed pixel nn = tid, k rows 0..15 each iter
    const int nn   = tid;
    const int n    = n0 + nn;
    const int ph   = n / FW;
    const int pw   = n - ph * FW;
    int ci = 0, r = 0;            // k = ci*9 + r, walked sequentially

    u64 acc[8][4];
#pragma unroll
    for (int i = 0; i < 8; i++)
#pragma unroll
        for (int p = 0; p < 4; p++) acc[i][p] = 0ull;

    for (int k0 = 0; k0 < KDIM; k0 += 16) {
        // ---- A tile: 64x16 weights, duplicated ----
        float4 v0 = *(const float4*)(a_src + k0 + a_kq);
        float4 v1 = *(const float4*)(a_src + k0 + a_kq + 4);
        // ---- B tile: im2col gather, 16 k-rows for pixel nn ----
        float bvals[16];
#pragma unroll
        for (int q = 0; q < 16; q++) {
            int rq = r;                   // current (ci, r)
            int dh = rq / 3 - 1;
            int dw = rq - (rq / 3) * 3 - 1;
            int hh = ph + dh, ww = pw + dw;
            float val = 0.f;
            if ((unsigned)hh < (unsigned)FH && (unsigned)ww < (unsigned)FW)
                val = feat[ci * HW + hh * FW + ww];
            bvals[q] = val;
            r++;
            if (r == 9) { r = 0; ci++; }
        }
        __syncthreads();   // previous compute done before overwrite
        *(u64*)&As2[a_kq + 0][2 * a_m] = dup2(v0.x);
        *(u64*)&As2[a_kq + 1][2 * a_m] = dup2(v0.y);
        *(u64*)&As2[a_kq + 2][2 * a_m] = dup2(v0.z);
        *(u64*)&As2[a_kq + 3][2 * a_m] = dup2(v0.w);
        *(u64*)&As2[a_kq + 4][2 * a_m] = dup2(v1.x);
        *(u64*)&As2[a_kq + 5][2 * a_m] = dup2(v1.y);
        *(u64*)&As2[a_kq + 6][2 * a_m] = dup2(v1.z);
        *(u64*)&As2[a_kq + 7][2 * a_m] = dup2(v1.w);
#pragma unroll
        for (int q = 0; q < 16; q++) Bs[q][nn] = bvals[q];
        __syncthreads();

#pragma unroll
        for (int kk = 0; kk < 16; kk++) {
            ulonglong2 aA = *(const ulonglong2*)&As2[kk][tmg * 16 + 0];
            ulonglong2 aB = *(const ulonglong2*)&As2[kk][tmg * 16 + 4];
            ulonglong2 aC = *(const ulonglong2*)&As2[kk][tmg * 16 + 8];
            ulonglong2 aD = *(const ulonglong2*)&As2[kk][tmg * 16 + 12];
            ulonglong2 b0 = *(const ulonglong2*)&Bs[kk][tng * 8];
            ulonglong2 b1 = *(const ulonglong2*)&Bs[kk][tng * 8 + 4];
            u64 a2[8] = {aA.x, aA.y, aB.x, aB.y, aC.x, aC.y, aD.x, aD.y};
            u64 b2[4] = {b0.x, b0.y, b1.x, b1.y};
#pragma unroll
            for (int i = 0; i < 8; i++)
#pragma unroll
                for (int p = 0; p < 4; p++)
                    acc[i][p] = ffma2(a2[i], b2[p], acc[i][p]);
        }
    }

    // epilogue: bias + relu -> g_x[co][n]
#pragma unroll
    for (int i = 0; i < 8; i++) {
        int co = co0 + tmg * 8 + i;
        float bv = bias[co];
        float* dst = &g_x[(size_t)co * HW + n0 + tng * 8];
#pragma unroll
        for (int p = 0; p < 4; p++) {
            float e0 = __uint_as_float((u32)(acc[i][p] & 0xFFFFFFFFull));
            float e1 = __uint_as_float((u32)(acc[i][p] >> 32));
            float2 o;
            o.x = fmaxf(e0 + bv, 0.f);
            o.y = fmaxf(e1 + bv, 0.f);
            *(float2*)(dst + 2 * p) = o;
        }
    }
}

// =====================================================================
// Kernel 2: fused 1x1 heads + softmax + anchor decode -> keys & boxes.
// 96 blocks x 256 threads: 64 pixels/block, 4-way K split per pixel.
// =====================================================================
__global__ void __launch_bounds__(256) head_kernel(
        const float* __restrict__ cls_w,  const float* __restrict__ cls_b,
        const float* __restrict__ bbox_w, const float* __restrict__ bbox_b,
        const float* __restrict__ im_info) {
    __shared__ float P[3][64][54];     // partials for K-quarters 1..3

    const int tid = threadIdx.x;
    const int nl  = tid & 63;
    const int half = tid >> 6;         // 0..3
    const int n = blockIdx.x * 64 + nl;
    const int cbase = half * 128;

    float acc[54];
#pragma unroll
    for (int j = 0; j < 54; j++) acc[j] = 0.f;

    for (int cb = 0; cb < 128; cb += 4) {
        int c = cbase + cb;
        float xv0 = g_x[(size_t)(c + 0) * HW + n];
        float xv1 = g_x[(size_t)(c + 1) * HW + n];
        float xv2 = g_x[(size_t)(c + 2) * HW + n];
        float xv3 = g_x[(size_t)(c + 3) * HW + n];
#pragma unroll
        for (int j = 0; j < 18; j++) {
            float4 wv = *(const float4*)(cls_w + j * CH + c);
            acc[j] += wv.x * xv0 + wv.y * xv1 + wv.z * xv2 + wv.w * xv3;
        }
#pragma unroll
        for (int j = 0; j < 36; j++) {
            float4 wv = *(const float4*)(bbox_w + j * CH + c);
            acc[18 + j] += wv.x * xv0 + wv.y * xv1 + wv.z * xv2 + wv.w * xv3;
        }
    }
    if (half > 0) {
#pragma unroll
        for (int j = 0; j < 54; j++) P[half - 1][nl][j] = acc[j];
    }
    __syncthreads();
    if (half != 0) return;

    float v[54];
#pragma unroll
    for (int j = 0; j < 54; j++) {
        float b = (j < 18) ? cls_b[j] : bbox_b[j - 18];
        v[j] = acc[j] + P[0][nl][j] + P[1][nl][j] + P[2][nl][j] + b;
    }

    const float im_h = im_info[0];
    const float im_w = im_info[1];
    const float ms   = 16.0f * im_info[2];
    const int  ph = n / FW;
    const int  pw = n - ph * FW;
    const float sx = (float)(pw * 16);
    const float sy = (float)(ph * 16);

#pragma unroll
    for (int a = 0; a < 9; a++) {
        float s0 = v[a], s1 = v[9 + a];
        float m  = fmaxf(s0, s1);
        float e0 = expf(s0 - m), e1 = expf(s1 - m);
        float score = e1 / (e0 + e1);

        float bx1 = c_anch[4 * a + 0] + sx;
        float by1 = c_anch[4 * a + 1] + sy;
        float bx2 = c_anch[4 * a + 2] + sx;
        float by2 = c_anch[4 * a + 3] + sy;
        float aw = bx2 - bx1 + 1.0f;
        float ah = by2 - by1 + 1.0f;
        float acx = bx1 + 0.5f * aw;
        float acy = by1 + 0.5f * ah;

        float d0 = v[18 + 4 * a + 0];
        float d1 = v[18 + 4 * a + 1];
        float d2 = v[18 + 4 * a + 2];
        float d3 = v[18 + 4 * a + 3];
        float cx = d0 * aw + acx;
        float cy = d1 * ah + acy;
        float pwid = expf(d2) * aw;
        float phei = expf(d3) * ah;

        float x1 = fminf(fmaxf(cx - 0.5f * pwid, 0.f), im_w - 1.0f);
        float y1 = fminf(fmaxf(cy - 0.5f * phei, 0.f), im_h - 1.0f);
        float x2 = fminf(fmaxf(cx + 0.5f * pwid, 0.f), im_w - 1.0f);
        float y2 = fminf(fmaxf(cy + 0.5f * phei, 0.f), im_h - 1.0f);

        bool keep = (x2 - x1 + 1.0f >= ms) && (y2 - y1 + 1.0f >= ms);
        float se = keep ? score : -__int_as_float(0x7F800000);  // -inf
        u32 sb = __float_as_uint(se);
        u32 mono = (sb & 0x80000000u) ? ~sb : (sb | 0x80000000u);
        int idx = n * 9 + a;
        g_keys[idx]  = ((u64)mono << 32) | (u64)(0xFFFFFFFFu - (u32)idx);
        g_boxes[idx] = make_float4(x1, y1, x2, y2);
    }
}

// ------------- pad keys [55296, 65536) with 0 (sorts last) -------------
__global__ void pad_keys_kernel() {
    int i = blockIdx.x * blockDim.x + threadIdx.x;
    if (i < NSORT - NANCH) g_keys[NANCH + i] = 0ull;
}

// =====================================================================
// Bitonic sort (descending) of 65536 u64 keys.
// =====================================================================
__device__ __forceinline__ void cswap(u64& a, u64& b, bool dec) {
    if (dec ? (a < b) : (a > b)) { u64 t = a; a = b; b = t; }
}

__global__ void __launch_bounds__(1024) bitonic_local_full() {
    __shared__ u64 S[4096];
    const int base = blockIdx.x * 4096;
    const int tid = threadIdx.x;
#pragma unroll
    for (int q = 0; q < 4; q++) S[tid + q * 1024] = g_keys[base + tid + q * 1024];
    __syncthreads();
    for (int k = 2; k <= 4096; k <<= 1) {
        for (int j = k >> 1; j > 0; j >>= 1) {
#pragma unroll
            for (int t0 = 0; t0 < 2; t0++) {
                int t = tid + t0 * 1024;
                int i = ((t & ~(j - 1)) << 1) | (t & (j - 1));
                int l = i + j;
                bool dec = (((base + i) & k) == 0);
                cswap(S[i], S[l], dec);
            }
            __syncthreads();
        }
    }
#pragma unroll
    for (int q = 0; q < 4; q++) g_keys[base + tid + q * 1024] = S[tid + q * 1024];
}

__global__ void __launch_bounds__(1024) bitonic_global_step(int k, int j) {
    int t = blockIdx.x * blockDim.x + threadIdx.x;   // 32768 pairs
    int i = ((t & ~(j - 1)) << 1) | (t & (j - 1));
    int l = i + j;
    bool dec = ((i & k) == 0);
    u64 a = g_keys[i], b = g_keys[l];
    if (dec ? (a < b) : (a > b)) { g_keys[i] = b; g_keys[l] = a; }
}

__global__ void __launch_bounds__(1024) bitonic_local_merge(int k) {
    __shared__ u64 S[4096];
    const int base = blockIdx.x * 4096;
    const int tid = threadIdx.x;
    const bool dec = ((base & k) == 0);   // k >= 8192: direction uniform per chunk
#pragma unroll
    for (int q = 0; q < 4; q++) S[tid + q * 1024] = g_keys[base + tid + q * 1024];
    __syncthreads();
    for (int j = 2048; j > 0; j >>= 1) {
#pragma unroll
        for (int t0 = 0; t0 < 2; t0++) {
            int t = tid + t0 * 1024;
            int i = ((t & ~(j - 1)) << 1) | (t & (j - 1));
            int l = i + j;
            cswap(S[i], S[l], dec);
        }
        __syncthreads();
    }
#pragma unroll
    for (int q = 0; q < 4; q++) g_keys[base + tid + q * 1024] = S[tid + q * 1024];
}

// =====================================================================
// Greedy NMS over sorted top-6000, 300 outputs.
// Single block, 1024 threads, 6 register-resident boxes/thread.
// Sorted descending => argmax(avail) == first unsuppressed index.
// =====================================================================
__global__ void __launch_bounds__(1024) nms_kernel(float* __restrict__ out) {
    const int tid = threadIdx.x;
    const int lane = tid & 31;
    const int warp = tid >> 5;

    float4 box[6];
    float  area[6];
    int    vld[6];
    unsigned sup = 0;

#pragma unroll
    for (int s = 0; s < 6; s++) {
        int p = s * 1024 + tid;
        if (p < PRE_NMS) {
            u64 key = g_keys[p];
            u32 idx = 0xFFFFFFFFu - (u32)(key & 0xFFFFFFFFull);
            float4 b = g_boxes[idx];
            box[s] = b;
            area[s] = (b.z - b.x + 1.0f) * (b.w - b.y + 1.0f);
            vld[s] = ((u32)(key >> 32) > 0x007FFFFFu) ? 1 : 0;
        } else {
            box[s] = make_float4(0.f, 0.f, 0.f, 0.f);
            area[s] = 0.f;
            vld[s] = 0;
            sup |= (1u << s);
        }
    }

    __shared__ int s_red[32];
    __shared__ int s_win;
    __shared__ float4 s_box;
    __shared__ float s_area;
    __shared__ int s_valid;

    for (int it = 0; it < POST_NMS; it++) {
        int mymin = 0x7FFFFFFF;
#pragma unroll
        for (int s = 0; s < 6; s++)
            if (!(sup & (1u << s))) { mymin = s * 1024 + tid; break; }
#pragma unroll
        for (int o = 16; o > 0; o >>= 1)
            mymin = min(mymin, __shfl_xor_sync(0xFFFFFFFFu, mymin, o));
        if (lane == 0) s_red[warp] = mymin;
        __syncthreads();
        if (warp == 0) {
            int v = s_red[lane];
#pragma unroll
            for (int o = 16; o > 0; o >>= 1)
                v = min(v, __shfl_xor_sync(0xFFFFFFFFu, v, o));
            if (lane == 0) s_win = v;
        }
        __syncthreads();
        int win = s_win;
        if (win != 0x7FFFFFFF && tid == (win & 1023)) {
            int s = win >> 10;
            s_box = box[s];
            s_area = area[s];
            s_valid = vld[s];
        }
        __syncthreads();

        if (tid == 0) {
            bool ok = (win != 0x7FFFFFFF) && s_valid;
            out[it * 5 + 0] = 0.f;
            out[it * 5 + 1] = ok ? s_box.x : 0.f;
            out[it * 5 + 2] = ok ? s_box.y : 0.f;
            out[it * 5 + 3] = ok ? s_box.z : 0.f;
            out[it * 5 + 4] = ok ? s_box.w : 0.f;
        }
        if (win != 0x7FFFFFFF) {
            float4 B = s_box;
            float A = s_area;
#pragma unroll
            for (int s = 0; s < 6; s++) {
                float xx1 = fmaxf(B.x, box[s].x);
                float yy1 = fmaxf(B.y, box[s].y);
                float xx2 = fminf(B.z, box[s].z);
                float yy2 = fminf(B.w, box[s].w);
                float inter = fmaxf(xx2 - xx1 + 1.0f, 0.f) *
                              fmaxf(yy2 - yy1 + 1.0f, 0.f);
                float iou = inter / (A + area[s] - inter);
                if (iou > 0.7f) sup |= (1u << s);
            }
        }
        __syncthreads();
    }
}

// =====================================================================
extern "C" void kernel_launch(void* const* d_in, const int* in_sizes, int n_in,
                              void* d_out, int out_size) {
    // Bind inputs by UNIQUE element count — robust to metadata ordering.
    const float *feat = 0, *im_info = 0, *conv_w = 0, *conv_b = 0;
    const float *cls_w = 0, *cls_b = 0, *bbox_w = 0, *bbox_b = 0;
    for (int i = 0; i < n_in; i++) {
        const float* p = (const float*)d_in[i];
        switch (in_sizes[i]) {
            case 3145728: feat    = p; break;
            case 3:       im_info = p; break;
            case 2359296: conv_w  = p; break;
            case 512:     conv_b  = p; break;
            case 9216:    cls_w   = p; break;
            case 18:      cls_b   = p; break;
            case 18432:   bbox_w  = p; break;
            case 36:      bbox_b  = p; break;
            default: break;
        }
    }
    if (!feat || !im_info || !conv_w || !conv_b || !cls_w || !cls_b || !bbox_w || !bbox_b) {
        feat    = (const float*)d_in[0];
        im_info = (const float*)d_in[1];
        conv_w  = (const float*)d_in[2];
        conv_b  = (const float*)d_in[3];
        cls_w   = (const float*)d_in[4];
        cls_b   = (const float*)d_in[5];
        bbox_w  = (const float*)d_in[6];
        bbox_b  = (const float*)d_in[7];
    }
    float* out = (float*)d_out;

    conv3_kernel<<<dim3(HW / 128, CH / 64), 128>>>(feat, conv_w, conv_b);
    head_kernel<<<HW / 64, 256>>>(cls_w, cls_b, bbox_w, bbox_b, im_info);
    pad_keys_kernel<<<(NSORT - NANCH + 255) / 256, 256>>>();

    bitonic_local_full<<<16, 1024>>>();
    for (int k = 8192; k <= 65536; k <<= 1) {
        for (int j = k >> 1; j >= 4096; j >>= 1)
            bitonic_global_step<<<32, 1024>>>(k, j);
        bitonic_local_merge<<<16, 1024>>>(k);
    }

    nms_kernel<<<1, 1024>>>(out);
}